// round 15
// baseline (speedup 1.0000x reference)
#include <cuda_runtime.h>
#include <cuda_bf16.h>
#include <math.h>
#include <stdint.h>

#define NQc 40000
#define EDc 128
#define NVc 43520
#define MPAD 40064   // 313*128

// ---------------- helpers ----------------
__device__ __forceinline__ void split2(float x, float y, uint32_t& hi, uint32_t& lo){
    __nv_bfloat16 hx = __float2bfloat16(x), hy = __float2bfloat16(y);
    float lx = x - __bfloat162float(hx), ly = y - __bfloat162float(hy);
    __nv_bfloat162 H = __halves2bfloat162(hx, hy);
    __nv_bfloat162 L = __floats2bfloat162_rn(lx, ly);
    hi = *(uint32_t*)&H; lo = *(uint32_t*)&L;
}
__device__ __forceinline__ void mma_bf16(float* c, const uint32_t* a, const uint32_t* b){
    asm volatile("mma.sync.aligned.m16n8k16.row.col.f32.bf16.bf16.f32 "
        "{%0,%1,%2,%3},{%4,%5,%6,%7},{%8,%9},{%0,%1,%2,%3};"
        : "+f"(c[0]),"+f"(c[1]),"+f"(c[2]),"+f"(c[3])
        : "r"(a[0]),"r"(a[1]),"r"(a[2]),"r"(a[3]),"r"(b[0]),"r"(b[1]));
}

// ---------------- scratch ----------------
__device__ float g_q   [NQc*EDc];
__device__ float g_v   [NVc*EDc];
__device__ float g_off [NQc*512];
__device__ float g_aw  [NQc*256];
__device__ float g_t1  [NQc*EDc];
__device__ float g_t2  [NQc*EDc];
__device__ float g_c1  [NQc*128];
__device__ float g_c2  [NQc*64];
__device__ float g_c3  [NQc*48];
__device__ float g_c4  [NQc*48];
__device__ float g_part[320*128];
__device__ float g_scale[128];
__device__ float g_shift[128];
__device__ int   g_maxidx;
__device__ uint2    g_apk [MPAD*64];
__device__ uint2    g_apk2[MPAD*64];
__device__ uint2    g_vpk [NVc*64];
__device__ uint32_t g_wb  [1310720];

// ---------------- elementwise ----------------
__global__ void copy_k(float* __restrict__ dst, const float* __restrict__ src, int n){
    int i = blockIdx.x*256 + threadIdx.x; if (i<n) dst[i]=src[i];
}

// ---------------- mask ----------------
__global__ void set_min_k(){ g_maxidx = (-2147483647 - 1); }
__global__ void rmax_k(const int* __restrict__ p, int n){
    int i = blockIdx.x*256 + threadIdx.x;
    int v = (i<n)? p[i] : (-2147483647 - 1);
    #pragma unroll
    for (int o=16;o>0;o>>=1) v = max(v, __shfl_xor_sync(0xffffffffu, v, o));
    __shared__ int sm_[8];
    if ((threadIdx.x&31)==0) sm_[threadIdx.x>>5]=v;
    __syncthreads();
    if (threadIdx.x==0){
        int m = sm_[0];
        #pragma unroll
        for (int j=1;j<8;j++) m = max(m, sm_[j]);
        atomicMax(&g_maxidx, m);
    }
}
__global__ void wmask_k(const int* __restrict__ p, float* __restrict__ o, int n){
    int i = blockIdx.x*256 + threadIdx.x;
    if (i<n) o[i] = (p[i] < g_maxidx) ? 1.0f : 0.0f;
}

// ---------------- split fp32 -> interleaved bf16 hi/lo plane ----------------
__global__ void splitk(const float* __restrict__ src, uint2* __restrict__ dst,
                       int Mrows, int Csrc, int Cd2, int total){
    int i = blockIdx.x*256 + threadIdx.x; if (i>=total) return;
    int row = i / Cd2, c2 = i - row*Cd2;
    float x=0.f, y=0.f;
    if (row < Mrows){
        int ch = c2*2;
        if (ch   < Csrc) x = src[(size_t)row*Csrc + ch];
        if (ch+1 < Csrc) y = src[(size_t)row*Csrc + ch + 1];
    }
    uint32_t h,l; split2(x,y,h,l);
    dst[i] = make_uint2(h,l);
}

// ---------------- split of (a+b), 128 channels ----------------
__global__ void split_add_k(const float* __restrict__ a, const float* __restrict__ b,
                            uint2* __restrict__ dst, int total){
    int i = blockIdx.x*256 + threadIdx.x; if (i>=total) return;
    int row = i >> 6, c2 = i & 63;
    float x=0.f, y=0.f;
    if (row < NQc){
        size_t o = (size_t)row*128 + c2*2;
        x = a[o] + b[o]; y = a[o+1] + b[o+1];
    }
    uint32_t h,l; split2(x,y,h,l);
    dst[i] = make_uint2(h,l);
}

// ---------------- weight permute (dense GEMM B [K][N]) ----------------
//   word = ((c*NS+s)*2048) + ks*1024 + wn*512 + nt*128 + lane*4 + reg*2 + part
__global__ void permB_k(const float* __restrict__ B, uint32_t* __restrict__ out,
                        int K, int N, int total){
    int i = blockIdx.x*256 + threadIdx.x; if (i>=total) return;
    int part = i & 1;
    int reg  = (i>>1) & 1;
    int lane = (i>>2) & 31;
    int nt   = (i>>7) & 3;
    int wn   = (i>>9) & 1;
    int ks   = (i>>10) & 1;
    int rest = i>>11; int NS=K>>5; int s=rest%NS, c=rest/NS;
    int n = c*64 + wn*32 + nt*8 + (lane>>2);
    int k = s*32 + ks*16 + reg*8 + (lane&3)*2;
    float x = (n<N)? B[(size_t)k*N+n] : 0.f;
    float y = (n<N)? B[(size_t)(k+1)*N+n] : 0.f;
    uint32_t h,l; split2(x,y,h,l);
    out[i] = part? l : h;
}

// ---------------- conv weight permute (OIHW -> fragment order) ----------------
__global__ void permBc_k(const float* __restrict__ w, uint32_t* __restrict__ out,
                         int OC, int IC, int spt, int KSKS, int total){
    int i = blockIdx.x*256 + threadIdx.x; if (i>=total) return;
    int part = i & 1;
    int reg  = (i>>1) & 1;
    int lane = (i>>2) & 31;
    int nt   = (i>>7) & 3;
    int wn   = (i>>9) & 1;
    int ks   = (i>>10) & 1;
    int rest = i>>11; int NS=KSKS*spt; int sg=rest%NS, c=rest/NS;
    int tap = sg/spt, sl = sg - tap*spt;
    int oc = c*64 + wn*32 + nt*8 + (lane>>2);
    int ic = sl*32 + ks*16 + reg*8 + (lane&3)*2;
    float x = (oc<OC && ic   < IC)? w[((size_t)oc*IC+ic  )*KSKS + tap] : 0.f;
    float y = (oc<OC && ic+1 < IC)? w[((size_t)oc*IC+ic+1)*KSKS + tap] : 0.f;
    uint32_t h,l; split2(x,y,h,l);
    out[i] = part? l : h;
}

// =====================================================================
// bf16x3 direct-fragment GEMM. NT=4: warp 32x32, 2 CTA/SM.
//                              NT=8: warp 32x64, 1 CTA/SM, BN=128.
// K = NS*32, fully unrolled. No smem, no syncs.
// =====================================================================
template<int NS, int NT>
__global__ void __launch_bounds__(256, (NT==4)?2:1) gemm_df_k(
    const uint2* __restrict__ Apk, const uint32_t* __restrict__ Bpk,
    const float* __restrict__ bias, float* __restrict__ C,
    uint2* __restrict__ Cpk,
    int M, int N, int relu)
{
    int tid=threadIdx.x, wid=tid>>5, lane=tid&31;
    int grp=lane>>2, tig=lane&3;
    int wm=wid>>1, wn=wid&1;
    int bm=blockIdx.y*128;
    const int Kw = NS*16;

    size_t rb[2][2];
    #pragma unroll
    for (int mt=0;mt<2;mt++)
        #pragma unroll
        for (int rh=0;rh<2;rh++)
            rb[mt][rh] = (size_t)(bm + (wm*2+mt)*16 + rh*8 + grp) * Kw;

    const uint32_t* Bc;
    if (NT==4) Bc = Bpk + (size_t)blockIdx.x * NS * 2048 + wn*512 + lane*4;
    else       Bc = Bpk + (size_t)(blockIdx.x*2 + wn) * NS * 2048 + lane*4;

    float cacc[2][NT][4];
    #pragma unroll
    for (int i=0;i<2;i++)
        #pragma unroll
        for (int j=0;j<NT;j++)
            #pragma unroll
            for (int r=0;r<4;r++) cacc[i][j][r]=0.f;

    #pragma unroll
    for (int s=0;s<NS;s++){
        int kws = s*16 + tig;
        #pragma unroll
        for (int ks=0;ks<2;ks++){
            const uint4* bp = (const uint4*)(Bc + s*2048 + ks*1024);
            uint4 bvs[NT];
            #pragma unroll
            for (int j=0;j<NT;j++) bvs[j] = bp[j*32];
            uint32_t ah[2][4], al[2][4];
            #pragma unroll
            for (int mt=0;mt<2;mt++)
                #pragma unroll
                for (int r=0;r<4;r++){
                    uint2 w = Apk[rb[mt][r&1] + kws + ks*8 + (r>>1)*4];
                    ah[mt][r]=w.x; al[mt][r]=w.y;
                }
            #pragma unroll
            for (int nt=0;nt<NT;nt++){
                uint32_t bh[2]={bvs[nt].x,bvs[nt].z}, bl[2]={bvs[nt].y,bvs[nt].w};
                #pragma unroll
                for (int mt=0;mt<2;mt++){
                    mma_bf16(cacc[mt][nt], ah[mt], bl);
                    mma_bf16(cacc[mt][nt], al[mt], bh);
                    mma_bf16(cacc[mt][nt], ah[mt], bh);
                }
            }
        }
    }

    int cd2 = N>>1;
    #pragma unroll
    for (int mt=0;mt<2;mt++){
        int r0 = bm + (wm*2+mt)*16 + grp;
        #pragma unroll
        for (int nt=0;nt<NT;nt++){
            int col = blockIdx.x*(16*NT) + wn*(8*NT) + nt*8 + tig*2;
            float bx = bias[col], by = bias[col+1];
            float o0=cacc[mt][nt][0]+bx, o1=cacc[mt][nt][1]+by;
            float o2=cacc[mt][nt][2]+bx, o3=cacc[mt][nt][3]+by;
            if (relu){ o0=fmaxf(o0,0.f); o1=fmaxf(o1,0.f); o2=fmaxf(o2,0.f); o3=fmaxf(o3,0.f); }
            if (C){
                if (r0   < M) *(float2*)&C[(size_t)r0*N+col]     = make_float2(o0,o1);
                if (r0+8 < M) *(float2*)&C[(size_t)(r0+8)*N+col] = make_float2(o2,o3);
            }
            if (Cpk){
                uint32_t h,l;
                if (r0   < M){ split2(o0,o1,h,l); Cpk[(size_t)r0*cd2 + (col>>1)]     = make_uint2(h,l); }
                if (r0+8 < M){ split2(o2,o3,h,l); Cpk[(size_t)(r0+8)*cd2 + (col>>1)] = make_uint2(h,l); }
            }
        }
    }
}

// =====================================================================
// bf16x3 direct-fragment implicit conv (NHWC 200x200). No smem, no syncs.
// =====================================================================
template<int KS, int NT>
__global__ void __launch_bounds__(256, (NT==4)?2:1) conv_df_k(
    const uint2* __restrict__ Apk, const uint32_t* __restrict__ Bpk,
    float* __restrict__ out, int ICP, int OC, int spt, int pad)
{
    int tid=threadIdx.x, wid=tid>>5, lane=tid&31;
    int grp=lane>>2, tig=lane&3;
    int wm=wid>>1, wn=wid&1;
    int bm=blockIdx.y*128;
    int Kw=ICP>>1;

    int py[2][2], px[2][2]; bool pv[2][2];
    #pragma unroll
    for (int mt=0;mt<2;mt++)
        #pragma unroll
        for (int rh=0;rh<2;rh++){
            int p = bm + (wm*2+mt)*16 + rh*8 + grp;
            pv[mt][rh] = (p<40000);
            int yy = p/200; py[mt][rh]=yy; px[mt][rh]=p-yy*200;
        }

    int S = KS*KS*spt;
    const uint32_t* Bc;
    if (NT==4) Bc = Bpk + (size_t)blockIdx.x * S * 2048 + wn*512 + lane*4;
    else       Bc = Bpk + (size_t)(blockIdx.x*2 + wn) * S * 2048 + lane*4;

    float cacc[2][NT][4];
    #pragma unroll
    for (int i=0;i<2;i++)
        #pragma unroll
        for (int j=0;j<NT;j++)
            #pragma unroll
            for (int r=0;r<4;r++) cacc[i][j][r]=0.f;

    int dy=-pad, dx=-pad, sl=0, tx=0;
    for (int s=0;s<S;s++){
        int rbase[2][2]; bool v[2][2];
        #pragma unroll
        for (int mt=0;mt<2;mt++)
            #pragma unroll
            for (int rh=0;rh<2;rh++){
                int sy=py[mt][rh]+dy, sx=px[mt][rh]+dx;
                bool ok = pv[mt][rh] && ((unsigned)sy<200u) && ((unsigned)sx<200u);
                v[mt][rh]=ok;
                rbase[mt][rh] = ok ? (sy*200+sx)*Kw : 0;
            }
        int kws = sl*16 + tig;
        #pragma unroll
        for (int ks=0;ks<2;ks++){
            const uint4* bp = (const uint4*)(Bc + s*2048 + ks*1024);
            uint4 bvs[NT];
            #pragma unroll
            for (int j=0;j<NT;j++) bvs[j] = bp[j*32];
            uint32_t ah[2][4], al[2][4];
            #pragma unroll
            for (int mt=0;mt<2;mt++)
                #pragma unroll
                for (int r=0;r<4;r++){
                    uint2 w = make_uint2(0u,0u);
                    if (v[mt][r&1]) w = Apk[rbase[mt][r&1] + kws + ks*8 + (r>>1)*4];
                    ah[mt][r]=w.x; al[mt][r]=w.y;
                }
            #pragma unroll
            for (int nt=0;nt<NT;nt++){
                uint32_t bh[2]={bvs[nt].x,bvs[nt].z}, bl[2]={bvs[nt].y,bvs[nt].w};
                #pragma unroll
                for (int mt=0;mt<2;mt++){
                    mma_bf16(cacc[mt][nt], ah[mt], bl);
                    mma_bf16(cacc[mt][nt], al[mt], bh);
                    mma_bf16(cacc[mt][nt], ah[mt], bh);
                }
            }
        }
        if (++sl==spt){ sl=0; if (++tx==KS){ tx=0; dx=-pad; dy++; } else dx++; }
    }

    #pragma unroll
    for (int mt=0;mt<2;mt++){
        int r0 = bm + (wm*2+mt)*16 + grp;
        #pragma unroll
        for (int nt=0;nt<NT;nt++){
            int col = blockIdx.x*(16*NT) + wn*(8*NT) + nt*8 + tig*2;
            if (col >= OC) continue;
            if (r0   < 40000) *(float2*)&out[(size_t)r0*OC+col]     = make_float2(cacc[mt][nt][0],cacc[mt][nt][1]);
            if (r0+8 < 40000) *(float2*)&out[(size_t)(r0+8)*OC+col] = make_float2(cacc[mt][nt][2],cacc[mt][nt][3]);
        }
    }
}

// ---------------- softmax over 32 ----------------
__global__ void softmax32_k(float* __restrict__ a){
    int warp = threadIdx.x>>5, lane = threadIdx.x&31;
    int row = blockIdx.x*8 + warp;
    float v = a[(size_t)row*32 + lane];
    float m = v;
    #pragma unroll
    for (int o=16;o>0;o>>=1) m = fmaxf(m, __shfl_xor_sync(0xffffffffu, m, o));
    float e = expf(v - m);
    float s = e;
    #pragma unroll
    for (int o=16;o>0;o>>=1) s += __shfl_xor_sync(0xffffffffu, s, o);
    a[(size_t)row*32 + lane] = e / s;
}

// ---------------- deformable sampling: 2 channels/thread, writes split plane ----------------
__global__ void __launch_bounds__(256) sample_split_k(
    const float* __restrict__ v, const float* __restrict__ off,
    const float* __restrict__ aw, uint2* __restrict__ apk)
{
    int t = blockIdx.x*256 + threadIdx.x;
    if (t >= NQc*64) return;
    int q = t >> 6, r = t & 63, h = r >> 3, dp = r & 7;
    int ch = h*16 + dp*2;
    float refx = ((float)(q % 200) + 0.5f) * (1.f/200.f);
    float refy = ((float)(q / 200) + 0.5f) * (1.f/200.f);
    const float* op = off + (size_t)(q*8 + h)*64;
    const float* ap = aw  + (size_t)(q*8 + h)*32;
    const int Ws_[4]={256,128,64,32};
    const int Hs_[4]={128,64,32,16};
    const int Bs_[4]={0,32768,40960,43008};
    float acc0 = 0.f, acc1 = 0.f;
    #pragma unroll
    for (int l=0;l<4;l++){
        int W=Ws_[l], Hh=Hs_[l], base=Bs_[l];
        float fW=(float)W, fH=(float)Hh;
        #pragma unroll
        for (int p=0;p<8;p++){
            float ox = op[l*16 + p*2];
            float oy = op[l*16 + p*2 + 1];
            float x = refx*fW + ox - 0.5f;
            float y = refy*fH + oy - 0.5f;
            float x0f = floorf(x), y0f = floorf(y);
            int x0 = (int)x0f, y0 = (int)y0f;
            float fx = x - x0f, fy = y - y0f;
            float a = ap[l*8 + p];
            float s0 = 0.f, s1 = 0.f;
            #pragma unroll
            for (int cy=0;cy<2;cy++){
                int yc = y0+cy;
                if (yc < 0 || yc >= Hh) continue;
                float wy = cy? fy : (1.f-fy);
                int rowb = base + yc*W;
                if (x0 >= 0 && x0 < W){
                    float2 g = *(const float2*)&v[(size_t)(rowb+x0)*128 + ch];
                    float w0 = (1.f-fx)*wy; s0 += w0*g.x; s1 += w0*g.y;
                }
                if (x0+1 >= 0 && x0+1 < W){
                    float2 g = *(const float2*)&v[(size_t)(rowb+x0+1)*128 + ch];
                    float w1 = fx*wy; s0 += w1*g.x; s1 += w1*g.y;
                }
            }
            acc0 += a * s0; acc1 += a * s1;
        }
    }
    uint32_t hh,ll; split2(acc0,acc1,hh,ll);
    apk[(size_t)q*64 + (ch>>1)] = make_uint2(hh,ll);
}

// ---------------- residual + LayerNorm, writes q fp32 + split plane ----------------
__global__ void ln_res_split_k(float* __restrict__ q, const float* __restrict__ r,
                               const float* __restrict__ g, const float* __restrict__ b,
                               uint2* __restrict__ apk, const float* __restrict__ addpos)
{
    int row = blockIdx.x, c = threadIdx.x;
    size_t idx = (size_t)row*128 + c;
    float x = q[idx] + r[idx];
    __shared__ float sm_[4];
    float s = x;
    #pragma unroll
    for (int o=16;o>0;o>>=1) s += __shfl_xor_sync(0xffffffffu, s, o);
    if ((c&31)==0) sm_[c>>5]=s;
    __syncthreads();
    float mean = (sm_[0]+sm_[1]+sm_[2]+sm_[3]) * (1.f/128.f);
    __syncthreads();
    float dlt = x - mean;
    float s2 = dlt*dlt;
    #pragma unroll
    for (int o=16;o>0;o>>=1) s2 += __shfl_xor_sync(0xffffffffu, s2, o);
    if ((c&31)==0) sm_[c>>5]=s2;
    __syncthreads();
    float var = (sm_[0]+sm_[1]+sm_[2]+sm_[3]) * (1.f/128.f);
    float val = dlt * rsqrtf(var + 1e-5f) * g[c] + b[c];
    q[idx] = val;
    float v2 = addpos ? (val + addpos[idx]) : val;
    float nb = __shfl_down_sync(0xffffffffu, v2, 1);
    if (!(c&1)){
        uint32_t h,l; split2(v2, nb, h, l);
        apk[(size_t)row*64 + (c>>1)] = make_uint2(h,l);
    }
}

// ---------------- BN stats + apply ----------------
__global__ void bn_partial_k(const float* __restrict__ x, int C, float* __restrict__ part){
    int c = threadIdx.x, b = blockIdx.x;
    int p0 = b*250;
    float s=0.f, q=0.f;
    for (int p=0;p<250;p++){
        float v = x[(size_t)(p0+p)*C + c];
        s += v; q += v*v;
    }
    part[(size_t)b*C + c] = s;
    part[(size_t)(160+b)*C + c] = q;
}
__global__ void bn_finish_k(const float* __restrict__ part, const float* __restrict__ g,
                            const float* __restrict__ bb, float* __restrict__ scale,
                            float* __restrict__ shift, int C)
{
    int c = threadIdx.x;
    float s=0.f, q=0.f;
    for (int b=0;b<160;b++){ s += part[(size_t)b*C + c]; q += part[(size_t)(160+b)*C + c]; }
    float m = s * (1.f/40000.f);
    float v = q * (1.f/40000.f) - m*m;
    float sc = g[c] * rsqrtf(v + 1e-5f);
    scale[c] = sc;
    shift[c] = bb[c] - m*sc;
}
__global__ void bn_apply_split_k(const float* __restrict__ x,
    const float* __restrict__ scale, const float* __restrict__ shift,
    int C, uint2* __restrict__ dst, int Cd2, int total)
{
    int i = blockIdx.x*256 + threadIdx.x; if (i>=total) return;
    int row = i / Cd2, c2 = i - row*Cd2;
    float a=0.f, b=0.f;
    if (row < 40000){
        int ch = c2*2;
        if (ch   < C) a = fmaxf(x[(size_t)row*C+ch  ]*scale[ch  ]+shift[ch  ], 0.f);
        if (ch+1 < C) b = fmaxf(x[(size_t)row*C+ch+1]*scale[ch+1]+shift[ch+1], 0.f);
    }
    uint32_t h,l; split2(a,b,h,l);
    dst[i] = make_uint2(h,l);
}

// ---------------- final BN + 1x1 conv (48 -> 21), NCHW output ----------------
__global__ void conv5_bn_k(const float* __restrict__ h4,
                           const float* __restrict__ scale, const float* __restrict__ shift,
                           const float* __restrict__ w, const float* __restrict__ b,
                           float* __restrict__ out)
{
    int t = blockIdx.x*256 + threadIdx.x;
    int p = t >> 5, cls = t & 31;
    if (p >= 40000 || cls >= 21) return;
    const float* hr = h4 + (size_t)p*48;
    const float* wr = w + cls*48;
    float s = b[cls];
    #pragma unroll
    for (int c=0;c<48;c++){
        float h = fmaxf(hr[c]*scale[c] + shift[c], 0.f);
        s += h*wr[c];
    }
    out[(size_t)cls*40000 + p] = s;
}

// ==================================================================
extern "C" void kernel_launch(void* const* d_in, const int* in_sizes, int n_in,
                              void* d_out, int out_size)
{
    const float* value = (const float*)d_in[0];
    const float* bq    = (const float*)d_in[1];
    const float* bpos  = (const float*)d_in[2];
    const int*   proj  = (const int*)  d_in[3];
    const float* Wv    = (const float*)d_in[4];
    const float* bv    = (const float*)d_in[5];
    const float* Woff  = (const float*)d_in[6];
    const float* boff  = (const float*)d_in[7];
    const float* Wattn = (const float*)d_in[8];
    const float* battn = (const float*)d_in[9];
    const float* Wout  = (const float*)d_in[10];
    const float* bout  = (const float*)d_in[11];
    const float* Wf1   = (const float*)d_in[12];
    const float* bf1   = (const float*)d_in[13];
    const float* Wf2   = (const float*)d_in[14];
    const float* bf2   = (const float*)d_in[15];
    const float* lng   = (const float*)d_in[16];
    const float* lnb   = (const float*)d_in[17];
    const float* cw1   = (const float*)d_in[18];
    const float* g1    = (const float*)d_in[19];
    const float* b1    = (const float*)d_in[20];
    const float* cw2   = (const float*)d_in[21];
    const float* g2    = (const float*)d_in[22];
    const float* b2    = (const float*)d_in[23];
    const float* cw3   = (const float*)d_in[24];
    const float* g3    = (const float*)d_in[25];
    const float* b3    = (const float*)d_in[26];
    const float* cw4   = (const float*)d_in[27];
    const float* g4    = (const float*)d_in[28];
    const float* b4    = (const float*)d_in[29];
    const float* objw  = (const float*)d_in[30];
    const float* objb  = (const float*)d_in[31];
    float* out = (float*)d_out;

    float *p_q,*p_v,*p_off,*p_aw,*p_t1,*p_t2;
    float *p_c1,*p_c2,*p_c3,*p_c4,*p_part,*p_scale,*p_shift;
    uint2 *p_apk,*p_apk2,*p_vpk; uint32_t *p_wb;
    cudaGetSymbolAddress((void**)&p_q,    g_q);
    cudaGetSymbolAddress((void**)&p_v,    g_v);
    cudaGetSymbolAddress((void**)&p_off,  g_off);
    cudaGetSymbolAddress((void**)&p_aw,   g_aw);
    cudaGetSymbolAddress((void**)&p_t1,   g_t1);
    cudaGetSymbolAddress((void**)&p_t2,   g_t2);
    cudaGetSymbolAddress((void**)&p_c1,   g_c1);
    cudaGetSymbolAddress((void**)&p_c2,   g_c2);
    cudaGetSymbolAddress((void**)&p_c3,   g_c3);
    cudaGetSymbolAddress((void**)&p_c4,   g_c4);
    cudaGetSymbolAddress((void**)&p_part, g_part);
    cudaGetSymbolAddress((void**)&p_scale,g_scale);
    cudaGetSymbolAddress((void**)&p_shift,g_shift);
    cudaGetSymbolAddress((void**)&p_apk,  g_apk);
    cudaGetSymbolAddress((void**)&p_apk2, g_apk2);
    cudaGetSymbolAddress((void**)&p_vpk,  g_vpk);
    cudaGetSymbolAddress((void**)&p_wb,   g_wb);

    const int NE = NQc*EDc;
    const int EB = (NE+255)/256;
    const int GM = 313;
    const int APT = MPAD*64;

    // weight offsets in g_wb (words)
    const int LW = 163840;
    const int oWv=0, oWoff=16384, oWattn=81920, oWout=114688, oWf1=131072, oWf2=147456;
    const int CB = 327680;
    const int oC1=CB, oC2=CB+802816, oC3=CB+876544, oC4=CB+913408;

    // ---- front-loaded so ncu (-s 5 -c 1) captures gemm_df_k ----
    permB_k<<<(16384+255)/256,256>>>(Wv, p_wb+oWv, 128,128, 16384);                 // 0
    splitk<<<(NVc*64+255)/256,256>>>(value, p_vpk, NVc, 128, 64, NVc*64);           // 1
    set_min_k<<<1,1>>>();                                                           // 2
    gemm_df_k<4,8><<<dim3(1,340),256>>>(p_vpk, p_wb+oWv, bv, p_v, nullptr, NVc,128,0); // 3
    rmax_k<<<(40000+255)/256,256>>>(proj, 40000);                                   // 4
    gemm_df_k<4,8><<<dim3(1,340),256>>>(p_vpk, p_wb+oWv, bv, p_v, nullptr, NVc,128,0); // 5
    if (out_size >= 880000)
        wmask_k<<<(40000+255)/256,256>>>(proj, out + 840000, 40000);
    copy_k<<<EB,256>>>(p_q, bq, NE);
    split_add_k<<<(APT+255)/256,256>>>(p_q, bpos, p_apk, APT);

    // remaining weight permutes
    permB_k<<<(65536+255)/256,256>>>(Woff,  p_wb+oWoff, 128,512, 65536);
    permB_k<<<(32768+255)/256,256>>>(Wattn, p_wb+oWattn,128,256, 32768);
    permB_k<<<(16384+255)/256,256>>>(Wout,  p_wb+oWout, 128,128, 16384);
    permB_k<<<(16384+255)/256,256>>>(Wf1,   p_wb+oWf1,  128,128, 16384);
    permB_k<<<(16384+255)/256,256>>>(Wf2,   p_wb+oWf2,  128,128, 16384);
    for (int i=1;i<2;i++){
        int L = i*LW;
        permB_k<<<(16384+255)/256,256>>>(Wv   +(size_t)i*128*128, p_wb+L+oWv,   128,128, 16384);
        permB_k<<<(65536+255)/256,256>>>(Woff +(size_t)i*128*512, p_wb+L+oWoff, 128,512, 65536);
        permB_k<<<(32768+255)/256,256>>>(Wattn+(size_t)i*128*256, p_wb+L+oWattn,128,256, 32768);
        permB_k<<<(16384+255)/256,256>>>(Wout +(size_t)i*128*128, p_wb+L+oWout, 128,128, 16384);
        permB_k<<<(16384+255)/256,256>>>(Wf1  +(size_t)i*128*128, p_wb+L+oWf1,  128,128, 16384);
        permB_k<<<(16384+255)/256,256>>>(Wf2  +(size_t)i*128*128, p_wb+L+oWf2,  128,128, 16384);
    }
    permBc_k<<<(802816+255)/256,256>>>(cw1, p_wb+oC1, 128,128, 4, 49, 802816);
    permBc_k<<<(73728 +255)/256,256>>>(cw2, p_wb+oC2,  64,128, 4,  9, 73728);
    permBc_k<<<(36864 +255)/256,256>>>(cw3, p_wb+oC3,  48, 64, 2,  9, 36864);
    permBc_k<<<(36864 +255)/256,256>>>(cw4, p_wb+oC4,  48, 48, 2,  9, 36864);

    // ---- encoder ----
    for (int i=0;i<2;i++){
        int L = i*LW;
        if (i==1)
            gemm_df_k<4,8><<<dim3(1,340),256>>>(p_vpk, p_wb+L+oWv, bv+i*128, p_v, nullptr, NVc,128,0);
        gemm_df_k<4,8><<<dim3(4,GM),256>>>(p_apk, p_wb+L+oWoff,  boff +i*512, p_off, nullptr, NQc,512,0);
        gemm_df_k<4,8><<<dim3(2,GM),256>>>(p_apk, p_wb+L+oWattn, battn+i*256, p_aw,  nullptr, NQc,256,0);
        softmax32_k<<<40000,256>>>(p_aw);
        sample_split_k<<<(NQc*64+255)/256,256>>>(p_v, p_off, p_aw, p_apk);
        gemm_df_k<4,8><<<dim3(1,GM),256>>>(p_apk, p_wb+L+oWout, bout+i*128, p_t1, nullptr, NQc,128,0);
        ln_res_split_k<<<40000,128>>>(p_q, p_t1, lng+(i*2+0)*EDc, lnb+(i*2+0)*EDc, p_apk, nullptr);
        gemm_df_k<4,8><<<dim3(1,GM),256>>>(p_apk, p_wb+L+oWf1, bf1+i*128, nullptr, p_apk2, NQc,128,1);
        gemm_df_k<4,8><<<dim3(1,GM),256>>>(p_apk2, p_wb+L+oWf2, bf2+i*128, p_t2, nullptr, NQc,128,0);
        ln_res_split_k<<<40000,128>>>(p_q, p_t2, lng+(i*2+1)*EDc, lnb+(i*2+1)*EDc, p_apk,
                                      (i==0)? bpos : nullptr);
    }

    // ---- conv head ----
    conv_df_k<7,8><<<dim3(1,GM),256>>>(p_apk, p_wb+oC1, p_c1, 128, 128, 4, 3);
    bn_partial_k<<<160,128>>>(p_c1, 128, p_part);
    bn_finish_k<<<1,128>>>(p_part, g1, b1, p_scale, p_shift, 128);
    bn_apply_split_k<<<(APT+255)/256,256>>>(p_c1, p_scale, p_shift, 128, p_vpk, 64, APT);

    conv_df_k<3,4><<<dim3(1,GM),256>>>(p_vpk, p_wb+oC2, p_c2, 128, 64, 4, 1);
    bn_partial_k<<<160,64>>>(p_c2, 64, p_part);
    bn_finish_k<<<1,64>>>(p_part, g2, b2, p_scale, p_shift, 64);
    bn_apply_split_k<<<(MPAD*32+255)/256,256>>>(p_c2, p_scale, p_shift, 64, p_apk, 32, MPAD*32);

    conv_df_k<3,4><<<dim3(1,GM),256>>>(p_apk, p_wb+oC3, p_c3, 64, 48, 2, 1);
    bn_partial_k<<<160,48>>>(p_c3, 48, p_part);
    bn_finish_k<<<1,48>>>(p_part, g3, b3, p_scale, p_shift, 48);
    bn_apply_split_k<<<(MPAD*32+255)/256,256>>>(p_c3, p_scale, p_shift, 48, p_vpk, 32, MPAD*32);

    conv_df_k<3,4><<<dim3(1,GM),256>>>(p_vpk, p_wb+oC4, p_c4, 64, 48, 2, 1);
    bn_partial_k<<<160,48>>>(p_c4, 48, p_part);
    bn_finish_k<<<1,48>>>(p_part, g4, b4, p_scale, p_shift, 48);

    conv5_bn_k<<<(40000*32)/256,256>>>(p_c4, p_scale, p_shift, objw, objb, out);
}

// round 16
// speedup vs baseline: 1.0805x; 1.0805x over previous
#include <cuda_runtime.h>
#include <cuda_bf16.h>
#include <math.h>
#include <stdint.h>

#define NQc 40000
#define EDc 128
#define NVc 43520
#define MPAD 40064   // 313*128

// ---------------- helpers ----------------
__device__ __forceinline__ void split2(float x, float y, uint32_t& hi, uint32_t& lo){
    __nv_bfloat16 hx = __float2bfloat16(x), hy = __float2bfloat16(y);
    float lx = x - __bfloat162float(hx), ly = y - __bfloat162float(hy);
    __nv_bfloat162 H = __halves2bfloat162(hx, hy);
    __nv_bfloat162 L = __floats2bfloat162_rn(lx, ly);
    hi = *(uint32_t*)&H; lo = *(uint32_t*)&L;
}
__device__ __forceinline__ void mma_bf16(float* c, const uint32_t* a, const uint32_t* b){
    asm volatile("mma.sync.aligned.m16n8k16.row.col.f32.bf16.bf16.f32 "
        "{%0,%1,%2,%3},{%4,%5,%6,%7},{%8,%9},{%0,%1,%2,%3};"
        : "+f"(c[0]),"+f"(c[1]),"+f"(c[2]),"+f"(c[3])
        : "r"(a[0]),"r"(a[1]),"r"(a[2]),"r"(a[3]),"r"(b[0]),"r"(b[1]));
}

// ---------------- scratch ----------------
__device__ float g_q   [NQc*EDc];
__device__ float g_v   [NVc*EDc];
__device__ float g_off [NQc*512];
__device__ float g_aw  [NQc*256];
__device__ float g_t1  [NQc*EDc];
__device__ float g_t2  [NQc*EDc];
__device__ float g_c1  [NQc*128];
__device__ float g_c2  [NQc*64];
__device__ float g_c3  [NQc*48];
__device__ float g_c4  [NQc*48];
__device__ float g_part[320*128];
__device__ float g_scale[128];
__device__ float g_shift[128];
__device__ int   g_maxidx;
__device__ uint2    g_apk [MPAD*64];
__device__ uint2    g_apk2[MPAD*64];
__device__ uint2    g_vpk [NVc*64];
__device__ uint32_t g_wb  [1310720];

// ---------------- elementwise ----------------
__global__ void copy_k(float* __restrict__ dst, const float* __restrict__ src, int n){
    int i = blockIdx.x*256 + threadIdx.x; if (i<n) dst[i]=src[i];
}

// ---------------- mask ----------------
__global__ void set_min_k(){ g_maxidx = (-2147483647 - 1); }
__global__ void rmax_k(const int* __restrict__ p, int n){
    int i = blockIdx.x*256 + threadIdx.x;
    int v = (i<n)? p[i] : (-2147483647 - 1);
    #pragma unroll
    for (int o=16;o>0;o>>=1) v = max(v, __shfl_xor_sync(0xffffffffu, v, o));
    __shared__ int sm_[8];
    if ((threadIdx.x&31)==0) sm_[threadIdx.x>>5]=v;
    __syncthreads();
    if (threadIdx.x==0){
        int m = sm_[0];
        #pragma unroll
        for (int j=1;j<8;j++) m = max(m, sm_[j]);
        atomicMax(&g_maxidx, m);
    }
}
__global__ void wmask_k(const int* __restrict__ p, float* __restrict__ o, int n){
    int i = blockIdx.x*256 + threadIdx.x;
    if (i<n) o[i] = (p[i] < g_maxidx) ? 1.0f : 0.0f;
}

// ---------------- split fp32 -> interleaved bf16 hi/lo plane ----------------
__global__ void splitk(const float* __restrict__ src, uint2* __restrict__ dst,
                       int Mrows, int Csrc, int Cd2, int total){
    int i = blockIdx.x*256 + threadIdx.x; if (i>=total) return;
    int row = i / Cd2, c2 = i - row*Cd2;
    float x=0.f, y=0.f;
    if (row < Mrows){
        int ch = c2*2;
        if (ch   < Csrc) x = src[(size_t)row*Csrc + ch];
        if (ch+1 < Csrc) y = src[(size_t)row*Csrc + ch + 1];
    }
    uint32_t h,l; split2(x,y,h,l);
    dst[i] = make_uint2(h,l);
}

// ---------------- split of (a+b), 128 channels ----------------
__global__ void split_add_k(const float* __restrict__ a, const float* __restrict__ b,
                            uint2* __restrict__ dst, int total){
    int i = blockIdx.x*256 + threadIdx.x; if (i>=total) return;
    int row = i >> 6, c2 = i & 63;
    float x=0.f, y=0.f;
    if (row < NQc){
        size_t o = (size_t)row*128 + c2*2;
        x = a[o] + b[o]; y = a[o+1] + b[o+1];
    }
    uint32_t h,l; split2(x,y,h,l);
    dst[i] = make_uint2(h,l);
}

// ---------------- weight permute (dense GEMM B [K][N]) ----------------
//   word = ((c*NS+s)*2048) + ks*1024 + wn*512 + nt*128 + lane*4 + reg*2 + part
__global__ void permB_k(const float* __restrict__ B, uint32_t* __restrict__ out,
                        int K, int N, int total){
    int i = blockIdx.x*256 + threadIdx.x; if (i>=total) return;
    int part = i & 1;
    int reg  = (i>>1) & 1;
    int lane = (i>>2) & 31;
    int nt   = (i>>7) & 3;
    int wn   = (i>>9) & 1;
    int ks   = (i>>10) & 1;
    int rest = i>>11; int NS=K>>5; int s=rest%NS, c=rest/NS;
    int n = c*64 + wn*32 + nt*8 + (lane>>2);
    int k = s*32 + ks*16 + reg*8 + (lane&3)*2;
    float x = (n<N)? B[(size_t)k*N+n] : 0.f;
    float y = (n<N)? B[(size_t)(k+1)*N+n] : 0.f;
    uint32_t h,l; split2(x,y,h,l);
    out[i] = part? l : h;
}

// ---------------- conv weight permute (OIHW -> fragment order) ----------------
__global__ void permBc_k(const float* __restrict__ w, uint32_t* __restrict__ out,
                         int OC, int IC, int spt, int KSKS, int total){
    int i = blockIdx.x*256 + threadIdx.x; if (i>=total) return;
    int part = i & 1;
    int reg  = (i>>1) & 1;
    int lane = (i>>2) & 31;
    int nt   = (i>>7) & 3;
    int wn   = (i>>9) & 1;
    int ks   = (i>>10) & 1;
    int rest = i>>11; int NS=KSKS*spt; int sg=rest%NS, c=rest/NS;
    int tap = sg/spt, sl = sg - tap*spt;
    int oc = c*64 + wn*32 + nt*8 + (lane>>2);
    int ic = sl*32 + ks*16 + reg*8 + (lane&3)*2;
    float x = (oc<OC && ic   < IC)? w[((size_t)oc*IC+ic  )*KSKS + tap] : 0.f;
    float y = (oc<OC && ic+1 < IC)? w[((size_t)oc*IC+ic+1)*KSKS + tap] : 0.f;
    uint32_t h,l; split2(x,y,h,l);
    out[i] = part? l : h;
}

// =====================================================================
// bf16x3 direct-fragment GEMM. NT=4: warp 32x32. NT=8: warp 32x64.
// Both at 2 CTA/SM (16 warps) for latency hiding. No smem, no syncs.
// =====================================================================
template<int NS, int NT>
__global__ void __launch_bounds__(256,2) gemm_df_k(
    const uint2* __restrict__ Apk, const uint32_t* __restrict__ Bpk,
    const float* __restrict__ bias, float* __restrict__ C,
    uint2* __restrict__ Cpk,
    int M, int N, int relu)
{
    int tid=threadIdx.x, wid=tid>>5, lane=tid&31;
    int grp=lane>>2, tig=lane&3;
    int wm=wid>>1, wn=wid&1;
    int bm=blockIdx.y*128;
    const int Kw = NS*16;

    size_t rb[2][2];
    #pragma unroll
    for (int mt=0;mt<2;mt++)
        #pragma unroll
        for (int rh=0;rh<2;rh++)
            rb[mt][rh] = (size_t)(bm + (wm*2+mt)*16 + rh*8 + grp) * Kw;

    const uint32_t* Bc;
    if (NT==4) Bc = Bpk + (size_t)blockIdx.x * NS * 2048 + wn*512 + lane*4;
    else       Bc = Bpk + (size_t)(blockIdx.x*2 + wn) * NS * 2048 + lane*4;

    float cacc[2][NT][4];
    #pragma unroll
    for (int i=0;i<2;i++)
        #pragma unroll
        for (int j=0;j<NT;j++)
            #pragma unroll
            for (int r=0;r<4;r++) cacc[i][j][r]=0.f;

    #pragma unroll
    for (int s=0;s<NS;s++){
        int kws = s*16 + tig;
        #pragma unroll
        for (int ks=0;ks<2;ks++){
            const uint4* bp = (const uint4*)(Bc + s*2048 + ks*1024);
            uint4 bvs[NT];
            #pragma unroll
            for (int j=0;j<NT;j++) bvs[j] = bp[j*32];
            uint32_t ah[2][4], al[2][4];
            #pragma unroll
            for (int mt=0;mt<2;mt++)
                #pragma unroll
                for (int r=0;r<4;r++){
                    uint2 w = Apk[rb[mt][r&1] + kws + ks*8 + (r>>1)*4];
                    ah[mt][r]=w.x; al[mt][r]=w.y;
                }
            #pragma unroll
            for (int nt=0;nt<NT;nt++){
                uint32_t bh[2]={bvs[nt].x,bvs[nt].z}, bl[2]={bvs[nt].y,bvs[nt].w};
                #pragma unroll
                for (int mt=0;mt<2;mt++){
                    mma_bf16(cacc[mt][nt], ah[mt], bl);
                    mma_bf16(cacc[mt][nt], al[mt], bh);
                    mma_bf16(cacc[mt][nt], ah[mt], bh);
                }
            }
        }
    }

    int cd2 = N>>1;
    #pragma unroll
    for (int mt=0;mt<2;mt++){
        int r0 = bm + (wm*2+mt)*16 + grp;
        #pragma unroll
        for (int nt=0;nt<NT;nt++){
            int col = blockIdx.x*(16*NT) + wn*(8*NT) + nt*8 + tig*2;
            float bx = bias[col], by = bias[col+1];
            float o0=cacc[mt][nt][0]+bx, o1=cacc[mt][nt][1]+by;
            float o2=cacc[mt][nt][2]+bx, o3=cacc[mt][nt][3]+by;
            if (relu){ o0=fmaxf(o0,0.f); o1=fmaxf(o1,0.f); o2=fmaxf(o2,0.f); o3=fmaxf(o3,0.f); }
            if (C){
                if (r0   < M) *(float2*)&C[(size_t)r0*N+col]     = make_float2(o0,o1);
                if (r0+8 < M) *(float2*)&C[(size_t)(r0+8)*N+col] = make_float2(o2,o3);
            }
            if (Cpk){
                uint32_t h,l;
                if (r0   < M){ split2(o0,o1,h,l); Cpk[(size_t)r0*cd2 + (col>>1)]     = make_uint2(h,l); }
                if (r0+8 < M){ split2(o2,o3,h,l); Cpk[(size_t)(r0+8)*cd2 + (col>>1)] = make_uint2(h,l); }
            }
        }
    }
}

// =====================================================================
// bf16x3 direct-fragment implicit conv (NHWC 200x200). No smem, no syncs.
// =====================================================================
template<int KS, int NT>
__global__ void __launch_bounds__(256,2) conv_df_k(
    const uint2* __restrict__ Apk, const uint32_t* __restrict__ Bpk,
    float* __restrict__ out, int ICP, int OC, int spt, int pad)
{
    int tid=threadIdx.x, wid=tid>>5, lane=tid&31;
    int grp=lane>>2, tig=lane&3;
    int wm=wid>>1, wn=wid&1;
    int bm=blockIdx.y*128;
    int Kw=ICP>>1;

    int py[2][2], px[2][2]; bool pv[2][2];
    #pragma unroll
    for (int mt=0;mt<2;mt++)
        #pragma unroll
        for (int rh=0;rh<2;rh++){
            int p = bm + (wm*2+mt)*16 + rh*8 + grp;
            pv[mt][rh] = (p<40000);
            int yy = p/200; py[mt][rh]=yy; px[mt][rh]=p-yy*200;
        }

    int S = KS*KS*spt;
    const uint32_t* Bc;
    if (NT==4) Bc = Bpk + (size_t)blockIdx.x * S * 2048 + wn*512 + lane*4;
    else       Bc = Bpk + (size_t)(blockIdx.x*2 + wn) * S * 2048 + lane*4;

    float cacc[2][NT][4];
    #pragma unroll
    for (int i=0;i<2;i++)
        #pragma unroll
        for (int j=0;j<NT;j++)
            #pragma unroll
            for (int r=0;r<4;r++) cacc[i][j][r]=0.f;

    int dy=-pad, dx=-pad, sl=0, tx=0;
    for (int s=0;s<S;s++){
        int rbase[2][2]; bool v[2][2];
        #pragma unroll
        for (int mt=0;mt<2;mt++)
            #pragma unroll
            for (int rh=0;rh<2;rh++){
                int sy=py[mt][rh]+dy, sx=px[mt][rh]+dx;
                bool ok = pv[mt][rh] && ((unsigned)sy<200u) && ((unsigned)sx<200u);
                v[mt][rh]=ok;
                rbase[mt][rh] = ok ? (sy*200+sx)*Kw : 0;
            }
        int kws = sl*16 + tig;
        #pragma unroll
        for (int ks=0;ks<2;ks++){
            const uint4* bp = (const uint4*)(Bc + s*2048 + ks*1024);
            uint4 bvs[NT];
            #pragma unroll
            for (int j=0;j<NT;j++) bvs[j] = bp[j*32];
            uint32_t ah[2][4], al[2][4];
            #pragma unroll
            for (int mt=0;mt<2;mt++)
                #pragma unroll
                for (int r=0;r<4;r++){
                    uint2 w = make_uint2(0u,0u);
                    if (v[mt][r&1]) w = Apk[rbase[mt][r&1] + kws + ks*8 + (r>>1)*4];
                    ah[mt][r]=w.x; al[mt][r]=w.y;
                }
            #pragma unroll
            for (int nt=0;nt<NT;nt++){
                uint32_t bh[2]={bvs[nt].x,bvs[nt].z}, bl[2]={bvs[nt].y,bvs[nt].w};
                #pragma unroll
                for (int mt=0;mt<2;mt++){
                    mma_bf16(cacc[mt][nt], ah[mt], bl);
                    mma_bf16(cacc[mt][nt], al[mt], bh);
                    mma_bf16(cacc[mt][nt], ah[mt], bh);
                }
            }
        }
        if (++sl==spt){ sl=0; if (++tx==KS){ tx=0; dx=-pad; dy++; } else dx++; }
    }

    #pragma unroll
    for (int mt=0;mt<2;mt++){
        int r0 = bm + (wm*2+mt)*16 + grp;
        #pragma unroll
        for (int nt=0;nt<NT;nt++){
            int col = blockIdx.x*(16*NT) + wn*(8*NT) + nt*8 + tig*2;
            if (col >= OC) continue;
            if (r0   < 40000) *(float2*)&out[(size_t)r0*OC+col]     = make_float2(cacc[mt][nt][0],cacc[mt][nt][1]);
            if (r0+8 < 40000) *(float2*)&out[(size_t)(r0+8)*OC+col] = make_float2(cacc[mt][nt][2],cacc[mt][nt][3]);
        }
    }
}

// ---------------- softmax over 32 ----------------
__global__ void softmax32_k(float* __restrict__ a){
    int warp = threadIdx.x>>5, lane = threadIdx.x&31;
    int row = blockIdx.x*8 + warp;
    float v = a[(size_t)row*32 + lane];
    float m = v;
    #pragma unroll
    for (int o=16;o>0;o>>=1) m = fmaxf(m, __shfl_xor_sync(0xffffffffu, m, o));
    float e = expf(v - m);
    float s = e;
    #pragma unroll
    for (int o=16;o>0;o>>=1) s += __shfl_xor_sync(0xffffffffu, s, o);
    a[(size_t)row*32 + lane] = e / s;
}

// ---------------- deformable sampling: 2 channels/thread, writes split plane ----------------
__global__ void __launch_bounds__(256) sample_split_k(
    const float* __restrict__ v, const float* __restrict__ off,
    const float* __restrict__ aw, uint2* __restrict__ apk)
{
    int t = blockIdx.x*256 + threadIdx.x;
    if (t >= NQc*64) return;
    int q = t >> 6, r = t & 63, h = r >> 3, dp = r & 7;
    int ch = h*16 + dp*2;
    float refx = ((float)(q % 200) + 0.5f) * (1.f/200.f);
    float refy = ((float)(q / 200) + 0.5f) * (1.f/200.f);
    const float* op = off + (size_t)(q*8 + h)*64;
    const float* ap = aw  + (size_t)(q*8 + h)*32;
    const int Ws_[4]={256,128,64,32};
    const int Hs_[4]={128,64,32,16};
    const int Bs_[4]={0,32768,40960,43008};
    float acc0 = 0.f, acc1 = 0.f;
    #pragma unroll
    for (int l=0;l<4;l++){
        int W=Ws_[l], Hh=Hs_[l], base=Bs_[l];
        float fW=(float)W, fH=(float)Hh;
        #pragma unroll
        for (int p=0;p<8;p++){
            float ox = op[l*16 + p*2];
            float oy = op[l*16 + p*2 + 1];
            float x = refx*fW + ox - 0.5f;
            float y = refy*fH + oy - 0.5f;
            float x0f = floorf(x), y0f = floorf(y);
            int x0 = (int)x0f, y0 = (int)y0f;
            float fx = x - x0f, fy = y - y0f;
            float a = ap[l*8 + p];
            float s0 = 0.f, s1 = 0.f;
            #pragma unroll
            for (int cy=0;cy<2;cy++){
                int yc = y0+cy;
                if (yc < 0 || yc >= Hh) continue;
                float wy = cy? fy : (1.f-fy);
                int rowb = base + yc*W;
                if (x0 >= 0 && x0 < W){
                    float2 g = *(const float2*)&v[(size_t)(rowb+x0)*128 + ch];
                    float w0 = (1.f-fx)*wy; s0 += w0*g.x; s1 += w0*g.y;
                }
                if (x0+1 >= 0 && x0+1 < W){
                    float2 g = *(const float2*)&v[(size_t)(rowb+x0+1)*128 + ch];
                    float w1 = fx*wy; s0 += w1*g.x; s1 += w1*g.y;
                }
            }
            acc0 += a * s0; acc1 += a * s1;
        }
    }
    uint32_t hh,ll; split2(acc0,acc1,hh,ll);
    apk[(size_t)q*64 + (ch>>1)] = make_uint2(hh,ll);
}

// ---------------- residual + LayerNorm, writes q fp32 + split plane ----------------
__global__ void ln_res_split_k(float* __restrict__ q, const float* __restrict__ r,
                               const float* __restrict__ g, const float* __restrict__ b,
                               uint2* __restrict__ apk, const float* __restrict__ addpos)
{
    int row = blockIdx.x, c = threadIdx.x;
    size_t idx = (size_t)row*128 + c;
    float x = q[idx] + r[idx];
    __shared__ float sm_[4];
    float s = x;
    #pragma unroll
    for (int o=16;o>0;o>>=1) s += __shfl_xor_sync(0xffffffffu, s, o);
    if ((c&31)==0) sm_[c>>5]=s;
    __syncthreads();
    float mean = (sm_[0]+sm_[1]+sm_[2]+sm_[3]) * (1.f/128.f);
    __syncthreads();
    float dlt = x - mean;
    float s2 = dlt*dlt;
    #pragma unroll
    for (int o=16;o>0;o>>=1) s2 += __shfl_xor_sync(0xffffffffu, s2, o);
    if ((c&31)==0) sm_[c>>5]=s2;
    __syncthreads();
    float var = (sm_[0]+sm_[1]+sm_[2]+sm_[3]) * (1.f/128.f);
    float val = dlt * rsqrtf(var + 1e-5f) * g[c] + b[c];
    q[idx] = val;
    float v2 = addpos ? (val + addpos[idx]) : val;
    float nb = __shfl_down_sync(0xffffffffu, v2, 1);
    if (!(c&1)){
        uint32_t h,l; split2(v2, nb, h, l);
        apk[(size_t)row*64 + (c>>1)] = make_uint2(h,l);
    }
}

// ---------------- BN stats + apply ----------------
__global__ void bn_partial_k(const float* __restrict__ x, int C, float* __restrict__ part){
    int c = threadIdx.x, b = blockIdx.x;
    int p0 = b*250;
    float s=0.f, q=0.f;
    for (int p=0;p<250;p++){
        float v = x[(size_t)(p0+p)*C + c];
        s += v; q += v*v;
    }
    part[(size_t)b*C + c] = s;
    part[(size_t)(160+b)*C + c] = q;
}
__global__ void bn_finish_k(const float* __restrict__ part, const float* __restrict__ g,
                            const float* __restrict__ bb, float* __restrict__ scale,
                            float* __restrict__ shift, int C)
{
    int c = threadIdx.x;
    float s=0.f, q=0.f;
    for (int b=0;b<160;b++){ s += part[(size_t)b*C + c]; q += part[(size_t)(160+b)*C + c]; }
    float m = s * (1.f/40000.f);
    float v = q * (1.f/40000.f) - m*m;
    float sc = g[c] * rsqrtf(v + 1e-5f);
    scale[c] = sc;
    shift[c] = bb[c] - m*sc;
}
__global__ void bn_apply_split_k(const float* __restrict__ x,
    const float* __restrict__ scale, const float* __restrict__ shift,
    int C, uint2* __restrict__ dst, int Cd2, int total)
{
    int i = blockIdx.x*256 + threadIdx.x; if (i>=total) return;
    int row = i / Cd2, c2 = i - row*Cd2;
    float a=0.f, b=0.f;
    if (row < 40000){
        int ch = c2*2;
        if (ch   < C) a = fmaxf(x[(size_t)row*C+ch  ]*scale[ch  ]+shift[ch  ], 0.f);
        if (ch+1 < C) b = fmaxf(x[(size_t)row*C+ch+1]*scale[ch+1]+shift[ch+1], 0.f);
    }
    uint32_t h,l; split2(a,b,h,l);
    dst[i] = make_uint2(h,l);
}

// ---------------- final BN + 1x1 conv (48 -> 21), NCHW output ----------------
__global__ void conv5_bn_k(const float* __restrict__ h4,
                           const float* __restrict__ scale, const float* __restrict__ shift,
                           const float* __restrict__ w, const float* __restrict__ b,
                           float* __restrict__ out)
{
    int t = blockIdx.x*256 + threadIdx.x;
    int p = t >> 5, cls = t & 31;
    if (p >= 40000 || cls >= 21) return;
    const float* hr = h4 + (size_t)p*48;
    const float* wr = w + cls*48;
    float s = b[cls];
    #pragma unroll
    for (int c=0;c<48;c++){
        float h = fmaxf(hr[c]*scale[c] + shift[c], 0.f);
        s += h*wr[c];
    }
    out[(size_t)cls*40000 + p] = s;
}

// ==================================================================
extern "C" void kernel_launch(void* const* d_in, const int* in_sizes, int n_in,
                              void* d_out, int out_size)
{
    const float* value = (const float*)d_in[0];
    const float* bq    = (const float*)d_in[1];
    const float* bpos  = (const float*)d_in[2];
    const int*   proj  = (const int*)  d_in[3];
    const float* Wv    = (const float*)d_in[4];
    const float* bv    = (const float*)d_in[5];
    const float* Woff  = (const float*)d_in[6];
    const float* boff  = (const float*)d_in[7];
    const float* Wattn = (const float*)d_in[8];
    const float* battn = (const float*)d_in[9];
    const float* Wout  = (const float*)d_in[10];
    const float* bout  = (const float*)d_in[11];
    const float* Wf1   = (const float*)d_in[12];
    const float* bf1   = (const float*)d_in[13];
    const float* Wf2   = (const float*)d_in[14];
    const float* bf2   = (const float*)d_in[15];
    const float* lng   = (const float*)d_in[16];
    const float* lnb   = (const float*)d_in[17];
    const float* cw1   = (const float*)d_in[18];
    const float* g1    = (const float*)d_in[19];
    const float* b1    = (const float*)d_in[20];
    const float* cw2   = (const float*)d_in[21];
    const float* g2    = (const float*)d_in[22];
    const float* b2    = (const float*)d_in[23];
    const float* cw3   = (const float*)d_in[24];
    const float* g3    = (const float*)d_in[25];
    const float* b3    = (const float*)d_in[26];
    const float* cw4   = (const float*)d_in[27];
    const float* g4    = (const float*)d_in[28];
    const float* b4    = (const float*)d_in[29];
    const float* objw  = (const float*)d_in[30];
    const float* objb  = (const float*)d_in[31];
    float* out = (float*)d_out;

    float *p_q,*p_v,*p_off,*p_aw,*p_t1,*p_t2;
    float *p_c1,*p_c2,*p_c3,*p_c4,*p_part,*p_scale,*p_shift;
    uint2 *p_apk,*p_apk2,*p_vpk; uint32_t *p_wb;
    cudaGetSymbolAddress((void**)&p_q,    g_q);
    cudaGetSymbolAddress((void**)&p_v,    g_v);
    cudaGetSymbolAddress((void**)&p_off,  g_off);
    cudaGetSymbolAddress((void**)&p_aw,   g_aw);
    cudaGetSymbolAddress((void**)&p_t1,   g_t1);
    cudaGetSymbolAddress((void**)&p_t2,   g_t2);
    cudaGetSymbolAddress((void**)&p_c1,   g_c1);
    cudaGetSymbolAddress((void**)&p_c2,   g_c2);
    cudaGetSymbolAddress((void**)&p_c3,   g_c3);
    cudaGetSymbolAddress((void**)&p_c4,   g_c4);
    cudaGetSymbolAddress((void**)&p_part, g_part);
    cudaGetSymbolAddress((void**)&p_scale,g_scale);
    cudaGetSymbolAddress((void**)&p_shift,g_shift);
    cudaGetSymbolAddress((void**)&p_apk,  g_apk);
    cudaGetSymbolAddress((void**)&p_apk2, g_apk2);
    cudaGetSymbolAddress((void**)&p_vpk,  g_vpk);
    cudaGetSymbolAddress((void**)&p_wb,   g_wb);

    const int NE = NQc*EDc;
    const int EB = (NE+255)/256;
    const int GM = 313;
    const int APT = MPAD*64;

    // weight offsets in g_wb (words)
    const int LW = 163840;
    const int oWv=0, oWoff=16384, oWattn=81920, oWout=114688, oWf1=131072, oWf2=147456;
    const int CB = 327680;
    const int oC1=CB, oC2=CB+802816, oC3=CB+876544, oC4=CB+913408;

    // ---- front-loaded so ncu (-s 5 -c 1) captures gemm_df_k ----
    permB_k<<<(16384+255)/256,256>>>(Wv, p_wb+oWv, 128,128, 16384);                 // 0
    splitk<<<(NVc*64+255)/256,256>>>(value, p_vpk, NVc, 128, 64, NVc*64);           // 1
    set_min_k<<<1,1>>>();                                                           // 2
    gemm_df_k<4,8><<<dim3(1,340),256>>>(p_vpk, p_wb+oWv, bv, p_v, nullptr, NVc,128,0); // 3
    rmax_k<<<(40000+255)/256,256>>>(proj, 40000);                                   // 4
    gemm_df_k<4,8><<<dim3(1,340),256>>>(p_vpk, p_wb+oWv, bv, p_v, nullptr, NVc,128,0); // 5
    if (out_size >= 880000)
        wmask_k<<<(40000+255)/256,256>>>(proj, out + 840000, 40000);
    copy_k<<<EB,256>>>(p_q, bq, NE);
    split_add_k<<<(APT+255)/256,256>>>(p_q, bpos, p_apk, APT);

    // remaining weight permutes
    permB_k<<<(65536+255)/256,256>>>(Woff,  p_wb+oWoff, 128,512, 65536);
    permB_k<<<(32768+255)/256,256>>>(Wattn, p_wb+oWattn,128,256, 32768);
    permB_k<<<(16384+255)/256,256>>>(Wout,  p_wb+oWout, 128,128, 16384);
    permB_k<<<(16384+255)/256,256>>>(Wf1,   p_wb+oWf1,  128,128, 16384);
    permB_k<<<(16384+255)/256,256>>>(Wf2,   p_wb+oWf2,  128,128, 16384);
    for (int i=1;i<2;i++){
        int L = i*LW;
        permB_k<<<(16384+255)/256,256>>>(Wv   +(size_t)i*128*128, p_wb+L+oWv,   128,128, 16384);
        permB_k<<<(65536+255)/256,256>>>(Woff +(size_t)i*128*512, p_wb+L+oWoff, 128,512, 65536);
        permB_k<<<(32768+255)/256,256>>>(Wattn+(size_t)i*128*256, p_wb+L+oWattn,128,256, 32768);
        permB_k<<<(16384+255)/256,256>>>(Wout +(size_t)i*128*128, p_wb+L+oWout, 128,128, 16384);
        permB_k<<<(16384+255)/256,256>>>(Wf1  +(size_t)i*128*128, p_wb+L+oWf1,  128,128, 16384);
        permB_k<<<(16384+255)/256,256>>>(Wf2  +(size_t)i*128*128, p_wb+L+oWf2,  128,128, 16384);
    }
    permBc_k<<<(802816+255)/256,256>>>(cw1, p_wb+oC1, 128,128, 4, 49, 802816);
    permBc_k<<<(73728 +255)/256,256>>>(cw2, p_wb+oC2,  64,128, 4,  9, 73728);
    permBc_k<<<(36864 +255)/256,256>>>(cw3, p_wb+oC3,  48, 64, 2,  9, 36864);
    permBc_k<<<(36864 +255)/256,256>>>(cw4, p_wb+oC4,  48, 48, 2,  9, 36864);

    // ---- encoder ----
    for (int i=0;i<2;i++){
        int L = i*LW;
        if (i==1)
            gemm_df_k<4,8><<<dim3(1,340),256>>>(p_vpk, p_wb+L+oWv, bv+i*128, p_v, nullptr, NVc,128,0);
        gemm_df_k<4,8><<<dim3(4,GM),256>>>(p_apk, p_wb+L+oWoff,  boff +i*512, p_off, nullptr, NQc,512,0);
        gemm_df_k<4,8><<<dim3(2,GM),256>>>(p_apk, p_wb+L+oWattn, battn+i*256, p_aw,  nullptr, NQc,256,0);
        softmax32_k<<<40000,256>>>(p_aw);
        sample_split_k<<<(NQc*64+255)/256,256>>>(p_v, p_off, p_aw, p_apk);
        gemm_df_k<4,8><<<dim3(1,GM),256>>>(p_apk, p_wb+L+oWout, bout+i*128, p_t1, nullptr, NQc,128,0);
        ln_res_split_k<<<40000,128>>>(p_q, p_t1, lng+(i*2+0)*EDc, lnb+(i*2+0)*EDc, p_apk, nullptr);
        gemm_df_k<4,8><<<dim3(1,GM),256>>>(p_apk, p_wb+L+oWf1, bf1+i*128, nullptr, p_apk2, NQc,128,1);
        gemm_df_k<4,8><<<dim3(1,GM),256>>>(p_apk2, p_wb+L+oWf2, bf2+i*128, p_t2, nullptr, NQc,128,0);
        ln_res_split_k<<<40000,128>>>(p_q, p_t2, lng+(i*2+1)*EDc, lnb+(i*2+1)*EDc, p_apk,
                                      (i==0)? bpos : nullptr);
    }

    // ---- conv head ----
    conv_df_k<7,8><<<dim3(1,GM),256>>>(p_apk, p_wb+oC1, p_c1, 128, 128, 4, 3);
    bn_partial_k<<<160,128>>>(p_c1, 128, p_part);
    bn_finish_k<<<1,128>>>(p_part, g1, b1, p_scale, p_shift, 128);
    bn_apply_split_k<<<(APT+255)/256,256>>>(p_c1, p_scale, p_shift, 128, p_vpk, 64, APT);

    conv_df_k<3,4><<<dim3(1,GM),256>>>(p_vpk, p_wb+oC2, p_c2, 128, 64, 4, 1);
    bn_partial_k<<<160,64>>>(p_c2, 64, p_part);
    bn_finish_k<<<1,64>>>(p_part, g2, b2, p_scale, p_shift, 64);
    bn_apply_split_k<<<(MPAD*32+255)/256,256>>>(p_c2, p_scale, p_shift, 64, p_apk, 32, MPAD*32);

    conv_df_k<3,4><<<dim3(1,GM),256>>>(p_apk, p_wb+oC3, p_c3, 64, 48, 2, 1);
    bn_partial_k<<<160,48>>>(p_c3, 48, p_part);
    bn_finish_k<<<1,48>>>(p_part, g3, b3, p_scale, p_shift, 48);
    bn_apply_split_k<<<(MPAD*32+255)/256,256>>>(p_c3, p_scale, p_shift, 48, p_vpk, 32, MPAD*32);

    conv_df_k<3,4><<<dim3(1,GM),256>>>(p_vpk, p_wb+oC4, p_c4, 64, 48, 2, 1);
    bn_partial_k<<<160,48>>>(p_c4, 48, p_part);
    bn_finish_k<<<1,48>>>(p_part, g4, b4, p_scale, p_shift, 48);

    conv5_bn_k<<<(40000*32)/256,256>>>(p_c4, p_scale, p_shift, objw, objb, out);
}